// round 8
// baseline (speedup 1.0000x reference)
#include <cuda_runtime.h>

#define BATCH 8
#define DIM 256
#define SEQ 16384
#define KK 3
#define HID 85
#define OUTC (DIM*KK)
#define BN_EPS 1e-5f
#define FULLM 0xffffffffu

#define NTHR 256
#define NCTA 1216                 // ~8 blocks/SM * 152 SMs
#define ITEMS_PER_BATCH (2*DIM)   // 256 pool rows + 256 conv rows
#define TOTAL_ITEMS (BATCH*ITEMS_PER_BATCH)
#define F4ROW (SEQ/4)             // 4096 f4 per row
#define F4THR (F4ROW/NTHR)        // 16 f4 per thread per row

// Device globals (no allocation allowed)
__device__ float g_pooled[BATCH * DIM];
__device__ float g_w[BATCH * OUTC];
__device__ unsigned g_work;
__device__ unsigned g_cnt[BATCH];
__device__ int g_ready[BATCH];

__global__ void reset_kernel() {
    if (threadIdx.x == 0) g_work = 0;
    if (threadIdx.x < BATCH) { g_cnt[threadIdx.x] = 0; g_ready[threadIdx.x] = 0; }
}

__global__ void __launch_bounds__(NTHR)
persistent_kernel(const float* __restrict__ x,
                  const float* __restrict__ w1,
                  const float* __restrict__ gamma,
                  const float* __restrict__ beta,
                  const float* __restrict__ mean,
                  const float* __restrict__ var,
                  const float* __restrict__ w2,
                  const float* __restrict__ b2,
                  const float* __restrict__ bias,
                  float* __restrict__ out) {
    const int tid = threadIdx.x;
    const int lane = tid & 31;

    __shared__ unsigned sh_item;
    __shared__ float sm[8];
    __shared__ int sh_mlp;
    __shared__ float ps[DIM];
    __shared__ float ys[HID];
    __shared__ float wsh[4];

    for (;;) {
        if (tid == 0) sh_item = atomicAdd(&g_work, 1u);
        __syncthreads();
        const unsigned item = sh_item;
        if (item >= TOTAL_ITEMS) return;

        const int b = item / ITEMS_PER_BATCH;
        const int within = item % ITEMS_PER_BATCH;

        if (within < DIM) {
            // ---------------- POOL item: row (b, within) ----------------
            const int c = within;
            const size_t rowoff = ((size_t)b * DIM + c) * SEQ;
            const float4* rp = (const float4*)(x + rowoff);

            float s = 0.f;
            #pragma unroll
            for (int g = 0; g < 2; g++) {
                float4 v[8];
                #pragma unroll
                for (int j = 0; j < 8; j++)
                    v[j] = rp[g * 2048 + j * NTHR + tid];
                #pragma unroll
                for (int j = 0; j < 8; j++)
                    s += (v[j].x + v[j].y) + (v[j].z + v[j].w);
            }
            #pragma unroll
            for (int off = 16; off > 0; off >>= 1)
                s += __shfl_down_sync(FULLM, s, off);
            if (lane == 0) sm[tid >> 5] = s;
            __syncthreads();
            if (tid == 0) {
                float t = 0.f;
                #pragma unroll
                for (int wgi = 0; wgi < 8; wgi++) t += sm[wgi];
                g_pooled[b * DIM + c] = t * (1.f / SEQ);
                __threadfence();                         // release pooled row
                unsigned r = atomicAdd(&g_cnt[b], 1u);
                sh_mlp = (r == DIM - 1);
            }
            __syncthreads();

            if (sh_mlp) {
                // last pool block of batch b: inline MLP
                __threadfence();                         // acquire all pooled[b]
                ps[tid] = __ldcg(g_pooled + b * DIM + tid);
                __syncthreads();
                if (tid < HID) {
                    const float* wr = w1 + tid * DIM;
                    float acc = 0.f;
                    #pragma unroll 8
                    for (int k = 0; k < DIM; k++) acc = fmaf(__ldg(wr + k), ps[k], acc);
                    float y = (acc - mean[tid]) * (gamma[tid] * rsqrtf(var[tid] + BN_EPS)) + beta[tid];
                    ys[tid] = fmaxf(y, 0.f);
                }
                __syncthreads();
                #pragma unroll
                for (int rep = 0; rep < 3; rep++) {
                    const int o = rep * NTHR + tid;      // 3*256 = 768 = OUTC
                    const float* wr = w2 + o * HID;
                    float acc = b2[o];
                    #pragma unroll 5
                    for (int h = 0; h < HID; h++) acc = fmaf(__ldg(wr + h), ys[h], acc);
                    g_w[b * OUTC + o] = acc;
                }
                __syncthreads();
                if (tid == 0) {
                    __threadfence();                     // release g_w[b]
                    g_ready[b] = 1;
                }
            }
        } else {
            // ---------------- CONV item: row (b, within-DIM) ----------------
            const int c = within - DIM;
            const size_t rowoff = ((size_t)b * DIM + c) * SEQ;

            if (tid == 0) {
                while (((volatile int*)g_ready)[b] == 0) __nanosleep(128);
            }
            __syncthreads();
            __threadfence();                             // acquire g_w[b]

            if (tid < 3) wsh[tid] = __ldcg(g_w + b * OUTC + c * KK + tid);
            if (tid == 3) wsh[3] = __ldg(bias + c);
            __syncthreads();
            const float w0 = wsh[0], w1v = wsh[1], w2v = wsh[2], bb = wsh[3];

            #pragma unroll
            for (int g = 0; g < 4; g++) {
                int t[4];
                float4 v[4];
                #pragma unroll
                for (int j = 0; j < 4; j++) {
                    t[j] = ((g * 4 + j) * NTHR + tid) * 4;
                    v[j] = *(const float4*)(x + rowoff + t[j]);
                }
                #pragma unroll
                for (int j = 0; j < 4; j++) {
                    float xl = __shfl_up_sync(FULLM, v[j].w, 1);
                    float xr = __shfl_down_sync(FULLM, v[j].x, 1);
                    if (lane == 0)
                        xl = (t[j] == 0) ? 0.f : __ldg(x + rowoff + t[j] - 1);
                    if (lane == 31)
                        xr = (t[j] + 4 >= SEQ) ? 0.f : __ldg(x + rowoff + t[j] + 4);

                    float4 o;
                    o.x = fmaf(w0, xl,     fmaf(w1v, v[j].x, fmaf(w2v, v[j].y, bb)));
                    o.y = fmaf(w0, v[j].x, fmaf(w1v, v[j].y, fmaf(w2v, v[j].z, bb)));
                    o.z = fmaf(w0, v[j].y, fmaf(w1v, v[j].z, fmaf(w2v, v[j].w, bb)));
                    o.w = fmaf(w0, v[j].z, fmaf(w1v, v[j].w, fmaf(w2v, xr,     bb)));

                    __stcs((float4*)(out + rowoff + t[j]), o);
                }
            }
        }
        __syncthreads();   // protect sh_item / shared reuse before next grab
    }
}

// ---------------------------------------------------------------------------
// Launch. Inputs (metadata order): x, w1, bn_gamma, bn_beta, bn_mean, bn_var,
// w2, b2, bias. Output: fp32 [8, 256, 16384].
// ---------------------------------------------------------------------------
extern "C" void kernel_launch(void* const* d_in, const int* in_sizes, int n_in,
                              void* d_out, int out_size) {
    const float* x     = (const float*)d_in[0];
    const float* w1    = (const float*)d_in[1];
    const float* gamma = (const float*)d_in[2];
    const float* beta  = (const float*)d_in[3];
    const float* mean  = (const float*)d_in[4];
    const float* var   = (const float*)d_in[5];
    const float* w2    = (const float*)d_in[6];
    const float* b2    = (const float*)d_in[7];
    const float* bias  = (const float*)d_in[8];
    float* out = (float*)d_out;

    reset_kernel<<<1, 32>>>();
    persistent_kernel<<<NCTA, NTHR>>>(x, w1, gamma, beta, mean, var,
                                      w2, b2, bias, out);
}